// round 13
// baseline (speedup 1.0000x reference)
#include <cuda_runtime.h>
#include <math_constants.h>

// Single-query attention: y = softmax(K @ q) @ V   (fp32, M=131072, D=256)
// ONE fused kernel. Streaming loop = R12's cp.async double-buffered smem
// staging (measured equal to best: ~6.5 TB/s, the practical HBM/LTS ceiling;
// low register count so the tail code below cannot disturb its scheduling).
// Combine = two-level last-arriver tree (37 groups x 16 CTAs), eliminating
// the second kernel launch (~4.5us of launch/ramp overhead).

#define M_TOTAL   131072
#define DIM       256
#define NCTA      592                      // 148 * 4, one wave
#define NWARPS    8
#define CHUNK_ROWS 8                       // one row per warp per chunk
#define CHUNK_FLOATS (CHUNK_ROWS * DIM)    // 2048 floats = 8KB
#define NCHUNKS   (M_TOTAL / CHUNK_ROWS)   // 16384

#define NGROUPS   37
#define GROUP_SZ  16                       // 37 * 16 = 592

// Scratch (allocation-free): ~660 KB
__device__ float g_part[NCTA][DIM];        // row layout: combiner reads coalesce
__device__ float g_m[NCTA];
__device__ float g_l[NCTA];
__device__ float g_part2[NGROUPS][DIM];
__device__ float g_m2[NGROUPS];
__device__ float g_l2[NGROUPS];
__device__ unsigned int g_cnt1[NGROUPS];   // zero-init; reset by final CTA
__device__ unsigned int g_cnt2;

__device__ __forceinline__ void cp16(float4* s, const float4* g) {
    unsigned int sa = (unsigned int)__cvta_generic_to_shared(s);
    asm volatile("cp.async.cg.shared.global [%0], [%1], 16;" :: "r"(sa), "l"(g));
}
#define CP_COMMIT() asm volatile("cp.async.commit_group;" ::: "memory")
#define CP_WAIT1()  asm volatile("cp.async.wait_group 1;" ::: "memory")

__global__ __launch_bounds__(256, 4)
void sqa_fused(const float* __restrict__ q,
               const float* __restrict__ K,
               const float* __restrict__ V,
               float* __restrict__ out) {
    const int tid  = threadIdx.x;
    const int warp = tid >> 5;
    const int lane = tid & 31;
    const int bid  = blockIdx.x;

    __shared__ float4 sK[2][CHUNK_FLOATS / 4];
    __shared__ float4 sV[2][CHUNK_FLOATS / 4];

    const float4 q0 = reinterpret_cast<const float4*>(q)[lane];
    const float4 q1 = reinterpret_cast<const float4*>(q)[lane + 32];

    float m = -CUDART_INF_F;
    float l = 0.0f;
    float4 a0 = make_float4(0.f, 0.f, 0.f, 0.f);
    float4 a1 = make_float4(0.f, 0.f, 0.f, 0.f);

    // ---- prefetch first chunk ----
    {
        const float4* gk = reinterpret_cast<const float4*>(K) + (size_t)bid * (CHUNK_FLOATS / 4);
        const float4* gv = reinterpret_cast<const float4*>(V) + (size_t)bid * (CHUNK_FLOATS / 4);
        cp16(&sK[0][tid],       gk + tid);
        cp16(&sK[0][tid + 256], gk + tid + 256);
        cp16(&sV[0][tid],       gv + tid);
        cp16(&sV[0][tid + 256], gv + tid + 256);
    }
    CP_COMMIT();

    int buf = 0;
    for (int c = bid; c < NCHUNKS; c += NCTA, buf ^= 1) {
        const int cn = c + NCTA;
        if (cn < NCHUNKS) {
            const float4* gk = reinterpret_cast<const float4*>(K) + (size_t)cn * (CHUNK_FLOATS / 4);
            const float4* gv = reinterpret_cast<const float4*>(V) + (size_t)cn * (CHUNK_FLOATS / 4);
            cp16(&sK[buf ^ 1][tid],       gk + tid);
            cp16(&sK[buf ^ 1][tid + 256], gk + tid + 256);
            cp16(&sV[buf ^ 1][tid],       gv + tid);
            cp16(&sV[buf ^ 1][tid + 256], gv + tid + 256);
        }
        CP_COMMIT();
        CP_WAIT1();
        __syncthreads();

        const float4* kr = &sK[buf][warp * (DIM / 4)];
        const float4  kA = kr[lane];
        const float4  kB = kr[lane + 32];

        float dd = kA.x * q0.x + kA.y * q0.y + kA.z * q0.z + kA.w * q0.w
                 + kB.x * q1.x + kB.y * q1.y + kB.z * q1.z + kB.w * q1.w;
        #pragma unroll
        for (int off = 16; off > 0; off >>= 1)
            dd += __shfl_xor_sync(0xffffffffu, dd, off);

        const float mnew  = fmaxf(m, dd);
        const float scale = __expf(m - mnew);   // exp(-inf)=0 on first chunk
        const float wv    = __expf(dd - mnew);
        l = l * scale + wv;
        m = mnew;

        const float4* vr = &sV[buf][warp * (DIM / 4)];
        const float4  vA = vr[lane];
        const float4  vB = vr[lane + 32];

        a0.x = a0.x * scale + wv * vA.x;
        a0.y = a0.y * scale + wv * vA.y;
        a0.z = a0.z * scale + wv * vA.z;
        a0.w = a0.w * scale + wv * vA.w;
        a1.x = a1.x * scale + wv * vB.x;
        a1.y = a1.y * scale + wv * vB.y;
        a1.z = a1.z * scale + wv * vB.z;
        a1.w = a1.w * scale + wv * vB.w;

        __syncthreads();
    }

    // ---------------- Merge 8 warps within the CTA ------------------------
    __shared__ float s_m[NWARPS];
    __shared__ float s_l[NWARPS];
    __shared__ float s_acc[NWARPS][DIM];
    __shared__ unsigned int s_last;

    if (lane == 0) { s_m[warp] = m; s_l[warp] = l; }
    float* dst = s_acc[warp];
    dst[lane * 4 + 0]       = a0.x;
    dst[lane * 4 + 1]       = a0.y;
    dst[lane * 4 + 2]       = a0.z;
    dst[lane * 4 + 3]       = a0.w;
    dst[128 + lane * 4 + 0] = a1.x;
    dst[128 + lane * 4 + 1] = a1.y;
    dst[128 + lane * 4 + 2] = a1.z;
    dst[128 + lane * 4 + 3] = a1.w;
    __syncthreads();

    float bm = s_m[0];
    #pragma unroll
    for (int w2 = 1; w2 < NWARPS; ++w2) bm = fmaxf(bm, s_m[w2]);

    float y = 0.0f;
    float L = 0.0f;
    #pragma unroll
    for (int w2 = 0; w2 < NWARPS; ++w2) {
        const float sf = __expf(s_m[w2] - bm);
        y += s_acc[w2][tid] * sf;
        L += s_l[w2] * sf;
    }

    g_part[bid][tid] = y;
    if (tid == 0) { g_m[bid] = bm; g_l[bid] = L; }

    // ---------------- Level 1: last CTA of each group combines ------------
    const int grp = bid / GROUP_SZ;
    __threadfence();   // release all this CTA's global stores
    __syncthreads();
    if (tid == 0)
        s_last = (atomicAdd(&g_cnt1[grp], 1u) == GROUP_SZ - 1u);
    __syncthreads();
    if (!s_last) return;
    __threadfence();   // acquire

    {
        const int i0 = grp * GROUP_SZ;
        float gm = g_m[i0];
        #pragma unroll
        for (int j = 1; j < GROUP_SZ; ++j) gm = fmaxf(gm, g_m[i0 + j]);

        float acc = 0.0f;
        float ll  = 0.0f;
        #pragma unroll 4
        for (int j = 0; j < GROUP_SZ; ++j) {
            const float sf = __expf(g_m[i0 + j] - gm);
            acc += g_part[i0 + j][tid] * sf;
            ll  += g_l[i0 + j] * sf;
        }
        g_part2[grp][tid] = acc;
        if (tid == 0) { g_m2[grp] = gm; g_l2[grp] = ll; }
    }

    // ---------------- Level 2: last group-combiner does final -------------
    __threadfence();
    __syncthreads();
    if (tid == 0)
        s_last = (atomicAdd(&g_cnt2, 1u) == NGROUPS - 1u);
    __syncthreads();
    if (!s_last) return;
    __threadfence();

    {
        float gm = g_m2[0];
        #pragma unroll
        for (int j = 1; j < NGROUPS; ++j) gm = fmaxf(gm, g_m2[j]);

        float acc = 0.0f;
        float ll  = 0.0f;
        #pragma unroll 4
        for (int j = 0; j < NGROUPS; ++j) {
            const float sf = __expf(g_m2[j] - gm);
            acc += g_part2[j][tid] * sf;
            ll  += g_l2[j] * sf;
        }
        out[tid] = acc / ll;
    }

    // Reset counters for next graph replay (only this CTA is alive here).
    if (tid < NGROUPS) g_cnt1[tid] = 0u;
    if (tid == 0) g_cnt2 = 0u;
}

extern "C" void kernel_launch(void* const* d_in, const int* in_sizes, int n_in,
                              void* d_out, int out_size) {
    const float* q = (const float*)d_in[0];
    const float* K = (const float*)d_in[1];
    const float* V = (const float*)d_in[2];
    float* out = (float*)d_out;

    sqa_fused<<<NCTA, 256>>>(q, K, V, out);
}

// round 14
// speedup vs baseline: 1.0031x; 1.0031x over previous
#include <cuda_runtime.h>
#include <math_constants.h>

// Single-query attention: y = softmax(K @ q) @ V   (fp32, M=131072, D=256)
// ONE fused kernel. Streaming loop = R12's cp.async double-buffered smem
// staging (measured equal to best: ~6.5 TB/s, the practical HBM/LTS ceiling;
// low register count so the tail code below cannot disturb its scheduling).
// Combine = two-level last-arriver tree (37 groups x 16 CTAs), eliminating
// the second kernel launch (~4.5us of launch/ramp overhead).

#define M_TOTAL   131072
#define DIM       256
#define NCTA      592                      // 148 * 4, one wave
#define NWARPS    8
#define CHUNK_ROWS 8                       // one row per warp per chunk
#define CHUNK_FLOATS (CHUNK_ROWS * DIM)    // 2048 floats = 8KB
#define NCHUNKS   (M_TOTAL / CHUNK_ROWS)   // 16384

#define NGROUPS   37
#define GROUP_SZ  16                       // 37 * 16 = 592

// Scratch (allocation-free): ~660 KB
__device__ float g_part[NCTA][DIM];        // row layout: combiner reads coalesce
__device__ float g_m[NCTA];
__device__ float g_l[NCTA];
__device__ float g_part2[NGROUPS][DIM];
__device__ float g_m2[NGROUPS];
__device__ float g_l2[NGROUPS];
__device__ unsigned int g_cnt1[NGROUPS];   // zero-init; reset by final CTA
__device__ unsigned int g_cnt2;

__device__ __forceinline__ void cp16(float4* s, const float4* g) {
    unsigned int sa = (unsigned int)__cvta_generic_to_shared(s);
    asm volatile("cp.async.cg.shared.global [%0], [%1], 16;" :: "r"(sa), "l"(g));
}
#define CP_COMMIT() asm volatile("cp.async.commit_group;" ::: "memory")
#define CP_WAIT1()  asm volatile("cp.async.wait_group 1;" ::: "memory")

__global__ __launch_bounds__(256, 4)
void sqa_fused(const float* __restrict__ q,
               const float* __restrict__ K,
               const float* __restrict__ V,
               float* __restrict__ out) {
    const int tid  = threadIdx.x;
    const int warp = tid >> 5;
    const int lane = tid & 31;
    const int bid  = blockIdx.x;

    __shared__ float4 sK[2][CHUNK_FLOATS / 4];
    __shared__ float4 sV[2][CHUNK_FLOATS / 4];

    const float4 q0 = reinterpret_cast<const float4*>(q)[lane];
    const float4 q1 = reinterpret_cast<const float4*>(q)[lane + 32];

    float m = -CUDART_INF_F;
    float l = 0.0f;
    float4 a0 = make_float4(0.f, 0.f, 0.f, 0.f);
    float4 a1 = make_float4(0.f, 0.f, 0.f, 0.f);

    // ---- prefetch first chunk ----
    {
        const float4* gk = reinterpret_cast<const float4*>(K) + (size_t)bid * (CHUNK_FLOATS / 4);
        const float4* gv = reinterpret_cast<const float4*>(V) + (size_t)bid * (CHUNK_FLOATS / 4);
        cp16(&sK[0][tid],       gk + tid);
        cp16(&sK[0][tid + 256], gk + tid + 256);
        cp16(&sV[0][tid],       gv + tid);
        cp16(&sV[0][tid + 256], gv + tid + 256);
    }
    CP_COMMIT();

    int buf = 0;
    for (int c = bid; c < NCHUNKS; c += NCTA, buf ^= 1) {
        const int cn = c + NCTA;
        if (cn < NCHUNKS) {
            const float4* gk = reinterpret_cast<const float4*>(K) + (size_t)cn * (CHUNK_FLOATS / 4);
            const float4* gv = reinterpret_cast<const float4*>(V) + (size_t)cn * (CHUNK_FLOATS / 4);
            cp16(&sK[buf ^ 1][tid],       gk + tid);
            cp16(&sK[buf ^ 1][tid + 256], gk + tid + 256);
            cp16(&sV[buf ^ 1][tid],       gv + tid);
            cp16(&sV[buf ^ 1][tid + 256], gv + tid + 256);
        }
        CP_COMMIT();
        CP_WAIT1();
        __syncthreads();

        const float4* kr = &sK[buf][warp * (DIM / 4)];
        const float4  kA = kr[lane];
        const float4  kB = kr[lane + 32];

        float dd = kA.x * q0.x + kA.y * q0.y + kA.z * q0.z + kA.w * q0.w
                 + kB.x * q1.x + kB.y * q1.y + kB.z * q1.z + kB.w * q1.w;
        #pragma unroll
        for (int off = 16; off > 0; off >>= 1)
            dd += __shfl_xor_sync(0xffffffffu, dd, off);

        const float mnew  = fmaxf(m, dd);
        const float scale = __expf(m - mnew);   // exp(-inf)=0 on first chunk
        const float wv    = __expf(dd - mnew);
        l = l * scale + wv;
        m = mnew;

        const float4* vr = &sV[buf][warp * (DIM / 4)];
        const float4  vA = vr[lane];
        const float4  vB = vr[lane + 32];

        a0.x = a0.x * scale + wv * vA.x;
        a0.y = a0.y * scale + wv * vA.y;
        a0.z = a0.z * scale + wv * vA.z;
        a0.w = a0.w * scale + wv * vA.w;
        a1.x = a1.x * scale + wv * vB.x;
        a1.y = a1.y * scale + wv * vB.y;
        a1.z = a1.z * scale + wv * vB.z;
        a1.w = a1.w * scale + wv * vB.w;

        __syncthreads();
    }

    // ---------------- Merge 8 warps within the CTA ------------------------
    __shared__ float s_m[NWARPS];
    __shared__ float s_l[NWARPS];
    __shared__ float s_acc[NWARPS][DIM];
    __shared__ unsigned int s_last;

    if (lane == 0) { s_m[warp] = m; s_l[warp] = l; }
    float* dst = s_acc[warp];
    dst[lane * 4 + 0]       = a0.x;
    dst[lane * 4 + 1]       = a0.y;
    dst[lane * 4 + 2]       = a0.z;
    dst[lane * 4 + 3]       = a0.w;
    dst[128 + lane * 4 + 0] = a1.x;
    dst[128 + lane * 4 + 1] = a1.y;
    dst[128 + lane * 4 + 2] = a1.z;
    dst[128 + lane * 4 + 3] = a1.w;
    __syncthreads();

    float bm = s_m[0];
    #pragma unroll
    for (int w2 = 1; w2 < NWARPS; ++w2) bm = fmaxf(bm, s_m[w2]);

    float y = 0.0f;
    float L = 0.0f;
    #pragma unroll
    for (int w2 = 0; w2 < NWARPS; ++w2) {
        const float sf = __expf(s_m[w2] - bm);
        y += s_acc[w2][tid] * sf;
        L += s_l[w2] * sf;
    }

    g_part[bid][tid] = y;
    if (tid == 0) { g_m[bid] = bm; g_l[bid] = L; }

    // ---------------- Level 1: last CTA of each group combines ------------
    const int grp = bid / GROUP_SZ;
    __threadfence();   // release all this CTA's global stores
    __syncthreads();
    if (tid == 0)
        s_last = (atomicAdd(&g_cnt1[grp], 1u) == GROUP_SZ - 1u);
    __syncthreads();
    if (!s_last) return;
    __threadfence();   // acquire

    {
        const int i0 = grp * GROUP_SZ;
        float gm = g_m[i0];
        #pragma unroll
        for (int j = 1; j < GROUP_SZ; ++j) gm = fmaxf(gm, g_m[i0 + j]);

        float acc = 0.0f;
        float ll  = 0.0f;
        #pragma unroll 4
        for (int j = 0; j < GROUP_SZ; ++j) {
            const float sf = __expf(g_m[i0 + j] - gm);
            acc += g_part[i0 + j][tid] * sf;
            ll  += g_l[i0 + j] * sf;
        }
        g_part2[grp][tid] = acc;
        if (tid == 0) { g_m2[grp] = gm; g_l2[grp] = ll; }
    }

    // ---------------- Level 2: last group-combiner does final -------------
    __threadfence();
    __syncthreads();
    if (tid == 0)
        s_last = (atomicAdd(&g_cnt2, 1u) == NGROUPS - 1u);
    __syncthreads();
    if (!s_last) return;
    __threadfence();

    {
        float gm = g_m2[0];
        #pragma unroll
        for (int j = 1; j < NGROUPS; ++j) gm = fmaxf(gm, g_m2[j]);

        float acc = 0.0f;
        float ll  = 0.0f;
        #pragma unroll 4
        for (int j = 0; j < NGROUPS; ++j) {
            const float sf = __expf(g_m2[j] - gm);
            acc += g_part2[j][tid] * sf;
            ll  += g_l2[j] * sf;
        }
        out[tid] = acc / ll;
    }

    // Reset counters for next graph replay (only this CTA is alive here).
    if (tid < NGROUPS) g_cnt1[tid] = 0u;
    if (tid == 0) g_cnt2 = 0u;
}

extern "C" void kernel_launch(void* const* d_in, const int* in_sizes, int n_in,
                              void* d_out, int out_size) {
    const float* q = (const float*)d_in[0];
    const float* K = (const float*)d_in[1];
    const float* V = (const float*)d_in[2];
    float* out = (float*)d_out;

    sqa_fused<<<NCTA, 256>>>(q, K, V, out);
}

// round 15
// speedup vs baseline: 1.1188x; 1.1153x over previous
#include <cuda_runtime.h>
#include <math_constants.h>

// Single-query attention: y = softmax(K @ q) @ V   (fp32, M=131072, D=256)
// Split structure (fusion rejected: 3x measured streaming degradation).
// Pass1: persistent single-wave (592 CTAs), RB=4 two-phase body, ~6.5TB/s
// (practical ceiling). Tail: R11 flat kernel. NEW: tail launched with
// Programmatic Dependent Launch (PDL) so its launch/ramp overlaps pass1's
// stragglers; cudaGridDependencySynchronize() gates the data reads.

#define M_TOTAL   131072
#define DIM       256
#define NCTA      592                      // 148 * 4, one wave
#define NWARPS    8
#define RB        4                        // rows per warp per chunk
#define CHUNK_ROWS (NWARPS * RB)           // 32
#define NCHUNKS   (M_TOTAL / CHUNK_ROWS)   // 4096

// Scratch (allocation-free): ~620 KB
__device__ float  g_partT[DIM][NCTA];      // transposed: [column][cta]
__device__ float2 g_ml[NCTA];              // packed (m, l)

__global__ __launch_bounds__(256, 4)
void sqa_pass1(const float* __restrict__ q,
               const float* __restrict__ K,
               const float* __restrict__ V) {
    const int tid  = threadIdx.x;
    const int warp = tid >> 5;
    const int lane = tid & 31;
    const int bid  = blockIdx.x;

    const float4 q0 = reinterpret_cast<const float4*>(q)[lane];
    const float4 q1 = reinterpret_cast<const float4*>(q)[lane + 32];

    float m = -CUDART_INF_F;
    float l = 0.0f;
    float4 a0 = make_float4(0.f, 0.f, 0.f, 0.f);
    float4 a1 = make_float4(0.f, 0.f, 0.f, 0.f);

    for (int c = bid; c < NCHUNKS; c += NCTA) {
        const int row0 = c * CHUNK_ROWS + warp * RB;

        // -------- K batch: 8 independent LDG.128 --------
        float4 k0[RB], k1[RB];
        #pragma unroll
        for (int j = 0; j < RB; ++j) {
            const float4* Kr =
                reinterpret_cast<const float4*>(K + (size_t)(row0 + j) * DIM);
            k0[j] = Kr[lane];
            k1[j] = Kr[lane + 32];
        }

        float d[RB];
        #pragma unroll
        for (int j = 0; j < RB; ++j) {
            float v = k0[j].x * q0.x + k0[j].y * q0.y + k0[j].z * q0.z + k0[j].w * q0.w
                    + k1[j].x * q1.x + k1[j].y * q1.y + k1[j].z * q1.z + k1[j].w * q1.w;
            #pragma unroll
            for (int off = 16; off > 0; off >>= 1)
                v += __shfl_xor_sync(0xffffffffu, v, off);
            d[j] = v;
        }

        // -------- online softmax update (chunk granularity) --------
        float mc = fmaxf(fmaxf(d[0], d[1]), fmaxf(d[2], d[3]));
        const float mnew  = fmaxf(m, mc);
        const float scale = __expf(m - mnew);   // exp(-inf)=0 on first chunk
        float w[RB];
        #pragma unroll
        for (int j = 0; j < RB; ++j) w[j] = __expf(d[j] - mnew);
        l = l * scale + (w[0] + w[1]) + (w[2] + w[3]);
        m = mnew;

        // -------- V batch: 8 independent LDG.128, weighted accumulate -----
        float4 v0[RB], v1[RB];
        #pragma unroll
        for (int j = 0; j < RB; ++j) {
            const float4* Vr =
                reinterpret_cast<const float4*>(V + (size_t)(row0 + j) * DIM);
            v0[j] = Vr[lane];
            v1[j] = Vr[lane + 32];
        }

        a0.x *= scale; a0.y *= scale; a0.z *= scale; a0.w *= scale;
        a1.x *= scale; a1.y *= scale; a1.z *= scale; a1.w *= scale;
        #pragma unroll
        for (int j = 0; j < RB; ++j) {
            a0.x += w[j] * v0[j].x;  a0.y += w[j] * v0[j].y;
            a0.z += w[j] * v0[j].z;  a0.w += w[j] * v0[j].w;
            a1.x += w[j] * v1[j].x;  a1.y += w[j] * v1[j].y;
            a1.z += w[j] * v1[j].z;  a1.w += w[j] * v1[j].w;
        }
    }

    // ---------------- Merge 8 warps within the CTA ------------------------
    __shared__ float s_m[NWARPS];
    __shared__ float s_l[NWARPS];
    __shared__ float s_acc[NWARPS][DIM];

    if (lane == 0) { s_m[warp] = m; s_l[warp] = l; }
    float* dst = s_acc[warp];
    dst[lane * 4 + 0]       = a0.x;
    dst[lane * 4 + 1]       = a0.y;
    dst[lane * 4 + 2]       = a0.z;
    dst[lane * 4 + 3]       = a0.w;
    dst[128 + lane * 4 + 0] = a1.x;
    dst[128 + lane * 4 + 1] = a1.y;
    dst[128 + lane * 4 + 2] = a1.z;
    dst[128 + lane * 4 + 3] = a1.w;
    __syncthreads();

    float bm = s_m[0];
    #pragma unroll
    for (int w2 = 1; w2 < NWARPS; ++w2) bm = fmaxf(bm, s_m[w2]);

    float y = 0.0f;
    float L = 0.0f;
    #pragma unroll
    for (int w2 = 0; w2 < NWARPS; ++w2) {
        const float sf = __expf(s_m[w2] - bm);
        y += s_acc[w2][tid] * sf;
        L += s_l[w2] * sf;
    }

    g_partT[tid][bid] = y;
    if (tid == 0) g_ml[bid] = make_float2(bm, L);

    // Signal PDL: this CTA's outputs are stored; dependents may proceed.
    cudaTriggerProgrammaticLaunchCompletion();
}

// Tail: 256 blocks (one per output column) x 256 threads. Launched with
// PDL so launch/ramp overlaps pass1; grid-dep sync gates the data reads.
__global__ __launch_bounds__(256)
void sqa_tail(float* __restrict__ out) {
    const int t    = threadIdx.x;
    const int warp = t >> 5;
    const int lane = t & 31;
    const int c    = blockIdx.x;

    __shared__ float s8m[NWARPS];
    __shared__ float s8l[NWARPS];
    __shared__ float s8a[NWARPS];

    const bool has3 = (t < NCTA - 512);

    // Wait for pass1's stores to be visible (PDL gate).
    cudaGridDependencySynchronize();

    // ---- front-issue ALL loads ----
    const float2 ml0 = g_ml[t];
    const float2 ml1 = g_ml[t + 256];
    const float2 ml2 = has3 ? g_ml[t + 512] : make_float2(-CUDART_INF_F, 0.0f);
    const float* row = g_partT[c];
    const float  r0  = row[t];
    const float  r1  = row[t + 256];
    const float  r2  = has3 ? row[t + 512] : 0.0f;

    // ---- round 1: block max ----
    float mv = fmaxf(fmaxf(ml0.x, ml1.x), ml2.x);
    #pragma unroll
    for (int off = 16; off > 0; off >>= 1)
        mv = fmaxf(mv, __shfl_xor_sync(0xffffffffu, mv, off));
    if (lane == 0) s8m[warp] = mv;
    __syncthreads();
    const float gmax = fmaxf(fmaxf(fmaxf(s8m[0], s8m[1]), fmaxf(s8m[2], s8m[3])),
                             fmaxf(fmaxf(s8m[4], s8m[5]), fmaxf(s8m[6], s8m[7])));

    const float e0 = __expf(ml0.x - gmax);
    const float e1 = __expf(ml1.x - gmax);
    const float e2 = has3 ? __expf(ml2.x - gmax) : 0.0f;

    // ---- round 2: joint (l, acc) reduction ----
    float ll  = ml0.y * e0 + ml1.y * e1 + ml2.y * e2;
    float acc = r0 * e0 + r1 * e1 + r2 * e2;
    #pragma unroll
    for (int off = 16; off > 0; off >>= 1) {
        ll  += __shfl_xor_sync(0xffffffffu, ll,  off);
        acc += __shfl_xor_sync(0xffffffffu, acc, off);
    }
    if (lane == 0) { s8l[warp] = ll; s8a[warp] = acc; }
    __syncthreads();
    if (t == 0) {
        const float L = ((s8l[0] + s8l[1]) + (s8l[2] + s8l[3]))
                      + ((s8l[4] + s8l[5]) + (s8l[6] + s8l[7]));
        const float A = ((s8a[0] + s8a[1]) + (s8a[2] + s8a[3]))
                      + ((s8a[4] + s8a[5]) + (s8a[6] + s8a[7]));
        out[c] = A / L;
    }
}

extern "C" void kernel_launch(void* const* d_in, const int* in_sizes, int n_in,
                              void* d_out, int out_size) {
    const float* q = (const float*)d_in[0];
    const float* K = (const float*)d_in[1];
    const float* V = (const float*)d_in[2];
    float* out = (float*)d_out;

    sqa_pass1<<<NCTA, 256>>>(q, K, V);

    // Tail with Programmatic Dependent Launch: launch/ramp overlaps pass1.
    cudaLaunchConfig_t cfg = {};
    cfg.gridDim  = dim3(DIM);
    cfg.blockDim = dim3(256);
    cfg.stream   = 0;
    cudaLaunchAttribute attrs[1];
    attrs[0].id = cudaLaunchAttributeProgrammaticStreamSerialization;
    attrs[0].val.programmaticStreamSerializationAllowed = 1;
    cfg.attrs    = attrs;
    cfg.numAttrs = 1;
    cudaLaunchKernelEx(&cfg, sqa_tail, out);
}

// round 16
// speedup vs baseline: 1.1251x; 1.0056x over previous
#include <cuda_runtime.h>
#include <math_constants.h>

// Single-query attention: y = softmax(K @ q) @ V   (fp32, M=131072, D=256)
// Pass1: persistent single-wave (592 = 148 SM x 4 CTAs), RB=4 two-phase
// body, ~6.6 TB/s (measured achieved-BW ceiling; invariant across LDG /
// cp.async / tuning). NEW: pass1 publishes the global max via one
// order-preserving atomicMax per CTA, so the tail needs NO max-reduction
// round -- single scalar load + one joint (l,acc) reduction.
// Tail resets the atomic via counter-gated last-arriver (replay-safe).

#define M_TOTAL   131072
#define DIM       256
#define NCTA      592                      // 148 * 4, one wave
#define NWARPS    8
#define RB        4                        // rows per warp per chunk
#define CHUNK_ROWS (NWARPS * RB)           // 32
#define NCHUNKS   (M_TOTAL / CHUNK_ROWS)   // 4096

// Scratch (allocation-free): ~620 KB
__device__ float  g_partT[DIM][NCTA];      // transposed: [column][cta]
__device__ float2 g_ml[NCTA];              // packed (m, l)
__device__ unsigned int g_gmax_u;          // order-preserving encoded max (0 = -inf)
__device__ unsigned int g_cnt;             // tail completion counter

// Order-preserving float <-> uint (monotone for all finite floats)
__device__ __forceinline__ unsigned int enc_f(float f) {
    unsigned int b = __float_as_uint(f);
    return (b & 0x80000000u) ? ~b : (b | 0x80000000u);
}
__device__ __forceinline__ float dec_f(unsigned int u) {
    unsigned int b = (u & 0x80000000u) ? (u ^ 0x80000000u) : ~u;
    return __uint_as_float(b);
}

__global__ __launch_bounds__(256, 4)
void sqa_pass1(const float* __restrict__ q,
               const float* __restrict__ K,
               const float* __restrict__ V) {
    const int tid  = threadIdx.x;
    const int warp = tid >> 5;
    const int lane = tid & 31;
    const int bid  = blockIdx.x;

    const float4 q0 = reinterpret_cast<const float4*>(q)[lane];
    const float4 q1 = reinterpret_cast<const float4*>(q)[lane + 32];

    float m = -CUDART_INF_F;
    float l = 0.0f;
    float4 a0 = make_float4(0.f, 0.f, 0.f, 0.f);
    float4 a1 = make_float4(0.f, 0.f, 0.f, 0.f);

    for (int c = bid; c < NCHUNKS; c += NCTA) {
        const int row0 = c * CHUNK_ROWS + warp * RB;

        // -------- K batch: 8 independent LDG.128 --------
        float4 k0[RB], k1[RB];
        #pragma unroll
        for (int j = 0; j < RB; ++j) {
            const float4* Kr =
                reinterpret_cast<const float4*>(K + (size_t)(row0 + j) * DIM);
            k0[j] = Kr[lane];
            k1[j] = Kr[lane + 32];
        }

        float d[RB];
        #pragma unroll
        for (int j = 0; j < RB; ++j) {
            float v = k0[j].x * q0.x + k0[j].y * q0.y + k0[j].z * q0.z + k0[j].w * q0.w
                    + k1[j].x * q1.x + k1[j].y * q1.y + k1[j].z * q1.z + k1[j].w * q1.w;
            #pragma unroll
            for (int off = 16; off > 0; off >>= 1)
                v += __shfl_xor_sync(0xffffffffu, v, off);
            d[j] = v;
        }

        // -------- online softmax update (chunk granularity) --------
        float mc = fmaxf(fmaxf(d[0], d[1]), fmaxf(d[2], d[3]));
        const float mnew  = fmaxf(m, mc);
        const float scale = __expf(m - mnew);   // exp(-inf)=0 on first chunk
        float w[RB];
        #pragma unroll
        for (int j = 0; j < RB; ++j) w[j] = __expf(d[j] - mnew);
        l = l * scale + (w[0] + w[1]) + (w[2] + w[3]);
        m = mnew;

        // -------- V batch: 8 independent LDG.128, weighted accumulate -----
        float4 v0[RB], v1[RB];
        #pragma unroll
        for (int j = 0; j < RB; ++j) {
            const float4* Vr =
                reinterpret_cast<const float4*>(V + (size_t)(row0 + j) * DIM);
            v0[j] = Vr[lane];
            v1[j] = Vr[lane + 32];
        }

        a0.x *= scale; a0.y *= scale; a0.z *= scale; a0.w *= scale;
        a1.x *= scale; a1.y *= scale; a1.z *= scale; a1.w *= scale;
        #pragma unroll
        for (int j = 0; j < RB; ++j) {
            a0.x += w[j] * v0[j].x;  a0.y += w[j] * v0[j].y;
            a0.z += w[j] * v0[j].z;  a0.w += w[j] * v0[j].w;
            a1.x += w[j] * v1[j].x;  a1.y += w[j] * v1[j].y;
            a1.z += w[j] * v1[j].z;  a1.w += w[j] * v1[j].w;
        }
    }

    // ---------------- Merge 8 warps within the CTA ------------------------
    __shared__ float s_m[NWARPS];
    __shared__ float s_l[NWARPS];
    __shared__ float s_acc[NWARPS][DIM];

    if (lane == 0) { s_m[warp] = m; s_l[warp] = l; }
    float* dst = s_acc[warp];
    dst[lane * 4 + 0]       = a0.x;
    dst[lane * 4 + 1]       = a0.y;
    dst[lane * 4 + 2]       = a0.z;
    dst[lane * 4 + 3]       = a0.w;
    dst[128 + lane * 4 + 0] = a1.x;
    dst[128 + lane * 4 + 1] = a1.y;
    dst[128 + lane * 4 + 2] = a1.z;
    dst[128 + lane * 4 + 3] = a1.w;
    __syncthreads();

    float bm = s_m[0];
    #pragma unroll
    for (int w2 = 1; w2 < NWARPS; ++w2) bm = fmaxf(bm, s_m[w2]);

    float y = 0.0f;
    float L = 0.0f;
    #pragma unroll
    for (int w2 = 0; w2 < NWARPS; ++w2) {
        const float sf = __expf(s_m[w2] - bm);
        y += s_acc[w2][tid] * sf;
        L += s_l[w2] * sf;
    }

    g_partT[tid][bid] = y;
    if (tid == 0) {
        g_ml[bid] = make_float2(bm, L);
        atomicMax(&g_gmax_u, enc_f(bm));   // publish global max (1 atomic/CTA)
    }
}

// Tail: 256 blocks (one per output column) x 256 threads.
// No max-reduction round: gmax is a single scalar load. One joint reduction.
// Last-arriver block (every block reads gmax BEFORE incrementing) resets
// g_gmax_u and g_cnt for the next graph replay.
__global__ __launch_bounds__(256)
void sqa_tail(float* __restrict__ out) {
    const int t    = threadIdx.x;
    const int warp = t >> 5;
    const int lane = t & 31;
    const int c    = blockIdx.x;

    __shared__ float s8l[NWARPS];
    __shared__ float s8a[NWARPS];

    const bool has3 = (t < NCTA - 512);

    // ---- front-issue ALL loads (gmax scalar + ml + row; all independent) --
    const float  gmax = dec_f(g_gmax_u);
    const float2 ml0  = g_ml[t];
    const float2 ml1  = g_ml[t + 256];
    const float2 ml2  = has3 ? g_ml[t + 512] : make_float2(0.0f, 0.0f);
    const float* row  = g_partT[c];
    const float  r0   = row[t];
    const float  r1   = row[t + 256];
    const float  r2   = has3 ? row[t + 512] : 0.0f;

    const float e0 = __expf(ml0.x - gmax);
    const float e1 = __expf(ml1.x - gmax);
    const float e2 = has3 ? __expf(ml2.x - gmax) : 0.0f;

    // ---- single JOINT (l, acc) reduction ----
    float ll  = ml0.y * e0 + ml1.y * e1 + ml2.y * e2;
    float acc = r0 * e0 + r1 * e1 + r2 * e2;
    #pragma unroll
    for (int off = 16; off > 0; off >>= 1) {
        ll  += __shfl_xor_sync(0xffffffffu, ll,  off);
        acc += __shfl_xor_sync(0xffffffffu, acc, off);
    }
    if (lane == 0) { s8l[warp] = ll; s8a[warp] = acc; }
    __syncthreads();
    if (t == 0) {
        const float L = ((s8l[0] + s8l[1]) + (s8l[2] + s8l[3]))
                      + ((s8l[4] + s8l[5]) + (s8l[6] + s8l[7]));
        const float A = ((s8a[0] + s8a[1]) + (s8a[2] + s8a[3]))
                      + ((s8a[4] + s8a[5]) + (s8a[6] + s8a[7]));
        out[c] = A / L;

        // Counter-gated reset: this block has already read gmax (above),
        // and every other block increments only after its own read, so the
        // last arriver can safely reset for the next graph replay.
        if (atomicAdd(&g_cnt, 1u) == (unsigned)(DIM - 1)) {
            g_gmax_u = 0u;   // encodes "most negative"
            g_cnt    = 0u;
        }
    }
}

extern "C" void kernel_launch(void* const* d_in, const int* in_sizes, int n_in,
                              void* d_out, int out_size) {
    const float* q = (const float*)d_in[0];
    const float* K = (const float*)d_in[1];
    const float* V = (const float*)d_in[2];
    float* out = (float*)d_out;

    sqa_pass1<<<NCTA, 256>>>(q, K, V);
    sqa_tail<<<DIM, 256>>>(out);
}